// round 1
// baseline (speedup 1.0000x reference)
#include <cuda_runtime.h>
#include <math.h>

// Problem constants
#define HH 96
#define WWID 96
#define HWSZ (HH * WWID)          // 9216
#define BATCH 8
#define P_TOT (BATCH * HWSZ)      // 73728 pixels
#define C_IN 256
#define C_O 128

// Scratch (device globals — allocation-free per harness rules)
__device__ __align__(16) float g_theta[(size_t)P_TOT * C_O];
__device__ __align__(16) float g_phi  [(size_t)P_TOT * C_O];
__device__ __align__(16) float g_g    [(size_t)P_TOT * C_O];
__device__ __align__(16) float g_wa   [(size_t)P_TOT * C_O];
__device__ float g_tnorm[P_TOT];
__device__ float g_pnorm[P_TOT];

// ---------------------------------------------------------------------------
// Pass 1: theta/phi/g = W (128x256) @ x_b (256xHW) + bias, pixel-major output.
// Also per-pixel L2 norms of theta and phi (including bias).
// Block: 256 threads, tile = 128 outputs x 64 pixels, k-tile 16.
// grid = (P_TOT/64, 3)  [y selects which weight]
// ---------------------------------------------------------------------------
__global__ __launch_bounds__(256) void pass1_gemm(
    const float* __restrict__ x,
    const float* __restrict__ w_theta, const float* __restrict__ b_theta,
    const float* __restrict__ w_phi,   const float* __restrict__ b_phi,
    const float* __restrict__ w_g,     const float* __restrict__ b_g)
{
    __shared__ __align__(16) float As[16][128];   // A transposed: As[k][o]
    __shared__ __align__(16) float Bs[16][64];    // Bs[k][p]
    __shared__ float red[16][64];

    const int tid = threadIdx.x;
    const int tx = tid & 15;        // pixel group (4 pixels each)
    const int ty = tid >> 4;        // output group (8 outputs each)
    const int p0 = blockIdx.x * 64;
    const int b  = p0 / HWSZ;
    const int hw0 = p0 % HWSZ;
    const int wsel = blockIdx.y;

    const float* wmat = (wsel == 0) ? w_theta : ((wsel == 1) ? w_phi : w_g);
    const float* bias = (wsel == 0) ? b_theta : ((wsel == 1) ? b_phi : b_g);
    float* outp       = (wsel == 0) ? g_theta : ((wsel == 1) ? g_phi : g_g);

    float acc[8][4];
#pragma unroll
    for (int r = 0; r < 8; ++r)
#pragma unroll
        for (int j = 0; j < 4; ++j) acc[r][j] = 0.f;

    const float4* w4 = (const float4*)wmat;   // [128][C_IN/4]
    const float4* x4 = (const float4*)x;

    for (int k0 = 0; k0 < C_IN; k0 += 16) {
        __syncthreads();
        // Load A tile (transpose to k-major)
#pragma unroll
        for (int i = 0; i < 2; ++i) {
            int chunk = tid * 2 + i;          // 0..511
            int o  = chunk >> 2;              // 0..127
            int kq = chunk & 3;               // 0..3
            float4 v = w4[o * (C_IN / 4) + (k0 >> 2) + kq];
            As[kq * 4 + 0][o] = v.x;
            As[kq * 4 + 1][o] = v.y;
            As[kq * 4 + 2][o] = v.z;
            As[kq * 4 + 3][o] = v.w;
        }
        // Load B tile (x slice, already k x p layout)
        {
            int kr = tid >> 4;                // 0..15
            int pq = tid & 15;                // 0..15 (float4 along pixels)
            size_t base = (((size_t)(b * C_IN + k0 + kr)) * HWSZ + hw0) >> 2;
            float4 v = x4[base + pq];
            *((float4*)&Bs[kr][pq * 4]) = v;
        }
        __syncthreads();
#pragma unroll
        for (int k = 0; k < 16; ++k) {
            float4 a0 = *(const float4*)&As[k][ty * 8];
            float4 a1 = *(const float4*)&As[k][ty * 8 + 4];
            float4 bb = *(const float4*)&Bs[k][tx * 4];
            float ar[8] = {a0.x, a0.y, a0.z, a0.w, a1.x, a1.y, a1.z, a1.w};
            float bv[4] = {bb.x, bb.y, bb.z, bb.w};
#pragma unroll
            for (int r = 0; r < 8; ++r)
#pragma unroll
                for (int j = 0; j < 4; ++j)
                    acc[r][j] += ar[r] * bv[j];
        }
    }

    // Epilogue: bias, store pixel-major, accumulate norms
    float bvv[8];
#pragma unroll
    for (int r = 0; r < 8; ++r) bvv[r] = bias[ty * 8 + r];

    float nrm[4] = {0.f, 0.f, 0.f, 0.f};
#pragma unroll
    for (int r = 0; r < 8; ++r)
#pragma unroll
        for (int j = 0; j < 4; ++j) {
            acc[r][j] += bvv[r];
            nrm[j] += acc[r][j] * acc[r][j];
        }

#pragma unroll
    for (int j = 0; j < 4; ++j) {
        int p = p0 + tx * 4 + j;
        float4 v0 = make_float4(acc[0][j], acc[1][j], acc[2][j], acc[3][j]);
        float4 v1 = make_float4(acc[4][j], acc[5][j], acc[6][j], acc[7][j]);
        float4* dst = (float4*)&outp[(size_t)p * C_O + ty * 8];
        dst[0] = v0;
        dst[1] = v1;
    }

    if (wsel < 2) {
        __syncthreads();   // As no longer needed; safe to reuse smem timing-wise
#pragma unroll
        for (int j = 0; j < 4; ++j) red[ty][tx * 4 + j] = nrm[j];
        __syncthreads();
        if (tid < 64) {
            float s = 0.f;
#pragma unroll
            for (int t = 0; t < 16; ++t) s += red[t][tid];
            float* np = (wsel == 0) ? g_tnorm : g_pnorm;
            np[p0 + tid] = sqrtf(s);
        }
    }
}

// ---------------------------------------------------------------------------
// Pass 2: per-pixel 3x3 neighbor cosine-sim softmax + weighted avg of g.
// One warp per pixel. grid = P_TOT/8, block = 256 (8 warps).
// ---------------------------------------------------------------------------
__global__ __launch_bounds__(256) void pass2_attn()
{
    const int warp = threadIdx.x >> 5;
    const int lane = threadIdx.x & 31;
    const int p = blockIdx.x * 8 + warp;
    const int b  = p / HWSZ;
    const int hw = p % HWSZ;
    const int h = hw / WWID;
    const int w = hw % WWID;

    const float4* th4 = (const float4*)g_theta;
    const float4* ph4 = (const float4*)g_phi;
    const float4* gg4 = (const float4*)g_g;

    float4 th = th4[(size_t)p * 32 + lane];
    float tn = g_tnorm[p];

    int pn[9];
    float sc[9];
#pragma unroll
    for (int n = 0; n < 9; ++n) {
        int di = n / 3 - 1, dj = n % 3 - 1;
        int hh = min(max(h + di, 0), HH - 1);
        int wn = min(max(w + dj, 0), WWID - 1);
        pn[n] = b * HWSZ + hh * WWID + wn;
        float4 ph = ph4[(size_t)pn[n] * 32 + lane];
        float d = th.x * ph.x + th.y * ph.y + th.z * ph.z + th.w * ph.w;
#pragma unroll
        for (int off = 16; off; off >>= 1)
            d += __shfl_xor_sync(0xffffffffu, d, off);
        float den = fmaxf(tn * g_pnorm[pn[n]], 1e-8f);
        sc[n] = d / den;
    }
    // softmax over 9 (redundant per lane, cheap)
    float m = sc[0];
#pragma unroll
    for (int n = 1; n < 9; ++n) m = fmaxf(m, sc[n]);
    float s = 0.f;
#pragma unroll
    for (int n = 0; n < 9; ++n) { sc[n] = __expf(sc[n] - m); s += sc[n]; }
    float inv = 1.f / s;

    float4 acc = make_float4(0.f, 0.f, 0.f, 0.f);
#pragma unroll
    for (int n = 0; n < 9; ++n) {
        float a = sc[n] * inv;
        float4 gv = gg4[(size_t)pn[n] * 32 + lane];
        acc.x += a * gv.x; acc.y += a * gv.y;
        acc.z += a * gv.z; acc.w += a * gv.w;
    }
    ((float4*)g_wa)[(size_t)p * 32 + lane] = acc;
}

// ---------------------------------------------------------------------------
// Pass 3: out = x + W_back (256x128) @ wa + b_back, written in [B,C,H,W].
// Block: 256 threads, tile = 128 out-channels x 64 pixels, k-tile 16, K=128.
// grid = (P_TOT/64, 2)  [y selects 128-channel half of C=256]
// ---------------------------------------------------------------------------
__global__ __launch_bounds__(256) void pass3_gemm(
    const float* __restrict__ x,
    const float* __restrict__ w_back, const float* __restrict__ b_back,
    float* __restrict__ out)
{
    __shared__ __align__(16) float As[16][128];   // As[k][c_local]
    __shared__ __align__(16) float Bs[16][68];    // Bs[k][p] (padded rows: 272B, 16B-aligned)

    const int tid = threadIdx.x;
    const int tx = tid & 15;
    const int ty = tid >> 4;
    const int p0 = blockIdx.x * 64;
    const int b  = p0 / HWSZ;
    const int hw0 = p0 % HWSZ;
    const int c0 = blockIdx.y * 128;

    float acc[8][4];
#pragma unroll
    for (int r = 0; r < 8; ++r)
#pragma unroll
        for (int j = 0; j < 4; ++j) acc[r][j] = 0.f;

    const float4* w4  = (const float4*)w_back;   // [256][C_O/4]
    const float4* wa4 = (const float4*)g_wa;     // [P][C_O/4]

    for (int k0 = 0; k0 < C_O; k0 += 16) {
        __syncthreads();
        // A tile: w_back rows c0..c0+127, transpose to k-major
#pragma unroll
        for (int i = 0; i < 2; ++i) {
            int chunk = tid * 2 + i;
            int o  = chunk >> 2;
            int kq = chunk & 3;
            float4 v = w4[(size_t)(c0 + o) * (C_O / 4) + (k0 >> 2) + kq];
            As[kq * 4 + 0][o] = v.x;
            As[kq * 4 + 1][o] = v.y;
            As[kq * 4 + 2][o] = v.z;
            As[kq * 4 + 3][o] = v.w;
        }
        // B tile: wa is pixel-major [P][128]; transpose to k x p
        {
            int pl = tid >> 2;     // 0..63
            int kq = tid & 3;      // 0..3
            float4 v = wa4[(size_t)(p0 + pl) * (C_O / 4) + (k0 >> 2) + kq];
            Bs[kq * 4 + 0][pl] = v.x;
            Bs[kq * 4 + 1][pl] = v.y;
            Bs[kq * 4 + 2][pl] = v.z;
            Bs[kq * 4 + 3][pl] = v.w;
        }
        __syncthreads();
#pragma unroll
        for (int k = 0; k < 16; ++k) {
            float4 a0 = *(const float4*)&As[k][ty * 8];
            float4 a1 = *(const float4*)&As[k][ty * 8 + 4];
            float4 bb = *(const float4*)&Bs[k][tx * 4];
            float ar[8] = {a0.x, a0.y, a0.z, a0.w, a1.x, a1.y, a1.z, a1.w};
            float bv[4] = {bb.x, bb.y, bb.z, bb.w};
#pragma unroll
            for (int r = 0; r < 8; ++r)
#pragma unroll
                for (int j = 0; j < 4; ++j)
                    acc[r][j] += ar[r] * bv[j];
        }
    }

    // Epilogue: residual add + bias, write in input layout
#pragma unroll
    for (int r = 0; r < 8; ++r) {
        int c = c0 + ty * 8 + r;
        float bb = b_back[c];
        size_t base = (((size_t)(b * C_IN + c)) * HWSZ + hw0) >> 2;
        float4 xv = ((const float4*)x)[base + tx];
        float4 o4;
        o4.x = xv.x + bb + acc[r][0];
        o4.y = xv.y + bb + acc[r][1];
        o4.z = xv.z + bb + acc[r][2];
        o4.w = xv.w + bb + acc[r][3];
        ((float4*)out)[base + tx] = o4;
    }
}

// ---------------------------------------------------------------------------
extern "C" void kernel_launch(void* const* d_in, const int* in_sizes, int n_in,
                              void* d_out, int out_size)
{
    const float* x       = (const float*)d_in[0];
    const float* w_theta = (const float*)d_in[1];
    const float* b_theta = (const float*)d_in[2];
    const float* w_phi   = (const float*)d_in[3];
    const float* b_phi   = (const float*)d_in[4];
    const float* w_g     = (const float*)d_in[5];
    const float* b_g     = (const float*)d_in[6];
    const float* w_back  = (const float*)d_in[7];
    const float* b_back  = (const float*)d_in[8];
    float* out = (float*)d_out;

    dim3 g1(P_TOT / 64, 3, 1);
    pass1_gemm<<<g1, 256>>>(x, w_theta, b_theta, w_phi, b_phi, w_g, b_g);

    pass2_attn<<<P_TOT / 8, 256>>>();

    dim3 g3(P_TOT / 64, 2, 1);
    pass3_gemm<<<g3, 256>>>(x, w_back, b_back, out);
}

// round 2
// speedup vs baseline: 1.7962x; 1.7962x over previous
#include <cuda_runtime.h>
#include <math.h>
#include <stdint.h>

// Problem constants
#define HH 96
#define WWID 96
#define HWSZ (HH * WWID)          // 9216
#define BATCH 8
#define P_TOT (BATCH * HWSZ)      // 73728 pixels
#define C_IN 256
#define C_O 128

// Scratch (device globals — allocation-free per harness rules)
__device__ __align__(16) float g_theta[(size_t)P_TOT * C_O];
__device__ __align__(16) float g_phi  [(size_t)P_TOT * C_O];
__device__ __align__(16) float g_g    [(size_t)P_TOT * C_O];
__device__ __align__(16) float g_wa   [(size_t)P_TOT * C_O];

__device__ __forceinline__ uint32_t f2tf32(float x) {
    uint32_t r;
    asm("cvt.rna.tf32.f32 %0, %1;" : "=r"(r) : "f"(x));
    return r;
}

__device__ __forceinline__ void mma_tf32(float c[4],
                                         uint32_t a0, uint32_t a1, uint32_t a2, uint32_t a3,
                                         uint32_t b0, uint32_t b1) {
    asm volatile(
        "mma.sync.aligned.m16n8k8.row.col.f32.tf32.tf32.f32 "
        "{%0,%1,%2,%3},{%4,%5,%6,%7},{%8,%9},{%0,%1,%2,%3};"
        : "+f"(c[0]), "+f"(c[1]), "+f"(c[2]), "+f"(c[3])
        : "r"(a0), "r"(a1), "r"(a2), "r"(a3), "r"(b0), "r"(b1));
}

// ---------------------------------------------------------------------------
// Pass 1 (tensor): theta/phi/g = W (128x256) @ x_b (256 x HW) + bias,
// output pixel-major [p][128].
// Block: 256 threads (8 warps, 2x4), tile 128 out x 128 px, k-tile 16.
// grid = (P_TOT/128, 3)
// ---------------------------------------------------------------------------
__global__ __launch_bounds__(256, 2) void pass1_gemm(
    const float* __restrict__ x,
    const float* __restrict__ w_theta, const float* __restrict__ b_theta,
    const float* __restrict__ w_phi,   const float* __restrict__ b_phi,
    const float* __restrict__ w_g,     const float* __restrict__ b_g)
{
    // smem: As[16][136] + Bs[16][136] (load phase)  UNION  stage[128][68] (epilogue)
    __shared__ __align__(16) float smbuf[8704];
    float* As = smbuf;                // [16][136]
    float* Bs = smbuf + 16 * 136;     // [16][136]
    float (*stage)[68] = (float(*)[68])smbuf;

    const int tid  = threadIdx.x;
    const int lane = tid & 31;
    const int warp = tid >> 5;
    const int warp_m = warp >> 2;     // 0..1  (64 out-channels)
    const int warp_n = warp & 3;      // 0..3  (32 pixels)
    const int q  = lane >> 2;         // 0..7
    const int kl = lane & 3;          // 0..3

    const int p0  = blockIdx.x * 128;
    const int b   = p0 / HWSZ;
    const int hw0 = p0 % HWSZ;
    const int wsel = blockIdx.y;

    const float* wmat = (wsel == 0) ? w_theta : ((wsel == 1) ? w_phi : w_g);
    const float* bias = (wsel == 0) ? b_theta : ((wsel == 1) ? b_phi : b_g);
    float* outp       = (wsel == 0) ? g_theta : ((wsel == 1) ? g_phi : g_g);

    float acc[4][4][4];
#pragma unroll
    for (int mt = 0; mt < 4; ++mt)
#pragma unroll
        for (int nt = 0; nt < 4; ++nt)
#pragma unroll
            for (int i = 0; i < 4; ++i) acc[mt][nt][i] = 0.f;

    const float4* w4 = (const float4*)wmat;   // [128][C_IN/4]
    const float4* x4 = (const float4*)x;

    for (int k0 = 0; k0 < C_IN; k0 += 16) {
        __syncthreads();
        // A tile: transpose weights into As[k][m] (tf32-rounded)
        {
            int m = tid >> 1;
            int half = tid & 1;
#pragma unroll
            for (int i = 0; i < 2; ++i) {
                int kq = half * 2 + i;          // f4 index within 16-k tile
                float4 v = w4[m * (C_IN / 4) + (k0 >> 2) + kq];
                int kk = kq * 4;
                As[(kk + 0) * 136 + m] = __uint_as_float(f2tf32(v.x));
                As[(kk + 1) * 136 + m] = __uint_as_float(f2tf32(v.y));
                As[(kk + 2) * 136 + m] = __uint_as_float(f2tf32(v.z));
                As[(kk + 3) * 136 + m] = __uint_as_float(f2tf32(v.w));
            }
        }
        // B tile: x slice (already k x p), row-copy with tf32 rounding
        {
#pragma unroll
            for (int i = 0; i < 2; ++i) {
                int idx = tid * 2 + i;          // 0..511
                int k   = idx >> 5;             // 0..15
                int pq  = idx & 31;             // f4 index along 128 px
                float4 v = x4[(((size_t)(b * C_IN + k0 + k)) * HWSZ + hw0) / 4 + pq];
                uint4 t;
                t.x = f2tf32(v.x); t.y = f2tf32(v.y);
                t.z = f2tf32(v.z); t.w = f2tf32(v.w);
                *(uint4*)&Bs[k * 136 + pq * 4] = t;
            }
        }
        __syncthreads();
#pragma unroll
        for (int ks = 0; ks < 16; ks += 8) {
            int kq = ks + kl;
            uint32_t af[4][4];
            uint32_t bf[4][2];
#pragma unroll
            for (int mt = 0; mt < 4; ++mt) {
                int m = warp_m * 64 + mt * 16 + q;
                af[mt][0] = __float_as_uint(As[kq * 136 + m]);
                af[mt][1] = __float_as_uint(As[kq * 136 + m + 8]);
                af[mt][2] = __float_as_uint(As[(kq + 4) * 136 + m]);
                af[mt][3] = __float_as_uint(As[(kq + 4) * 136 + m + 8]);
            }
#pragma unroll
            for (int nt = 0; nt < 4; ++nt) {
                int pc = warp_n * 32 + nt * 8 + q;
                bf[nt][0] = __float_as_uint(Bs[kq * 136 + pc]);
                bf[nt][1] = __float_as_uint(Bs[(kq + 4) * 136 + pc]);
            }
#pragma unroll
            for (int mt = 0; mt < 4; ++mt)
#pragma unroll
                for (int nt = 0; nt < 4; ++nt)
                    mma_tf32(acc[mt][nt], af[mt][0], af[mt][1], af[mt][2], af[mt][3],
                             bf[nt][0], bf[nt][1]);
        }
    }

    // bias per thread-row
    float bias_v[4][2];
#pragma unroll
    for (int mt = 0; mt < 4; ++mt)
#pragma unroll
        for (int hi = 0; hi < 2; ++hi)
            bias_v[mt][hi] = bias[warp_m * 64 + mt * 16 + q + hi * 8];

    // Epilogue: stage in [px][ch] chunks of 64 channels, coalesced stores
#pragma unroll
    for (int h = 0; h < 2; ++h) {
        __syncthreads();
        if (warp_m == h) {
#pragma unroll
            for (int mt = 0; mt < 4; ++mt)
#pragma unroll
                for (int nt = 0; nt < 4; ++nt)
#pragma unroll
                    for (int i = 0; i < 4; ++i) {
                        int px = warp_n * 32 + nt * 8 + 2 * kl + (i & 1);
                        int ch = mt * 16 + q + 8 * (i >> 1);
                        stage[px][ch] = acc[mt][nt][i] + bias_v[mt][i >> 1];
                    }
        }
        __syncthreads();
#pragma unroll
        for (int it = 0; it < 8; ++it) {
            int g = tid + it * 256;
            int px = g >> 4;          // 0..127
            int f  = g & 15;          // f4 within 64-ch chunk
            float4 v = *(float4*)&stage[px][f * 4];
            ((float4*)outp)[(size_t)(p0 + px) * 32 + h * 16 + f] = v;
        }
    }
}

// ---------------------------------------------------------------------------
// Pass 2: per-pixel 3x3 cosine-sim softmax + weighted avg of g.
// Norms fused here (data is loaded anyway). One warp per pixel.
// ---------------------------------------------------------------------------
__global__ __launch_bounds__(256) void pass2_attn()
{
    const int warp = threadIdx.x >> 5;
    const int lane = threadIdx.x & 31;
    const int p = blockIdx.x * 8 + warp;
    const int b  = p / HWSZ;
    const int hw = p % HWSZ;
    const int h = hw / WWID;
    const int w = hw % WWID;

    const float4* th4 = (const float4*)g_theta;
    const float4* ph4 = (const float4*)g_phi;
    const float4* gg4 = (const float4*)g_g;

    float4 th = th4[(size_t)p * 32 + lane];

    // theta norm
    float tt = th.x * th.x + th.y * th.y + th.z * th.z + th.w * th.w;
#pragma unroll
    for (int off = 16; off; off >>= 1)
        tt += __shfl_xor_sync(0xffffffffu, tt, off);
    float tn = sqrtf(tt);

    int pn[9];
    float sc[9];
#pragma unroll
    for (int n = 0; n < 9; ++n) {
        int di = n / 3 - 1, dj = n % 3 - 1;
        int hh = min(max(h + di, 0), HH - 1);
        int wn = min(max(w + dj, 0), WWID - 1);
        pn[n] = b * HWSZ + hh * WWID + wn;
        float4 ph = ph4[(size_t)pn[n] * 32 + lane];
        float d  = th.x * ph.x + th.y * ph.y + th.z * ph.z + th.w * ph.w;
        float pp = ph.x * ph.x + ph.y * ph.y + ph.z * ph.z + ph.w * ph.w;
#pragma unroll
        for (int off = 16; off; off >>= 1) {
            d  += __shfl_xor_sync(0xffffffffu, d, off);
            pp += __shfl_xor_sync(0xffffffffu, pp, off);
        }
        float den = fmaxf(tn * sqrtf(pp), 1e-8f);
        sc[n] = d / den;
    }
    float m = sc[0];
#pragma unroll
    for (int n = 1; n < 9; ++n) m = fmaxf(m, sc[n]);
    float s = 0.f;
#pragma unroll
    for (int n = 0; n < 9; ++n) { sc[n] = __expf(sc[n] - m); s += sc[n]; }
    float inv = 1.f / s;

    float4 acc = make_float4(0.f, 0.f, 0.f, 0.f);
#pragma unroll
    for (int n = 0; n < 9; ++n) {
        float a = sc[n] * inv;
        float4 gv = gg4[(size_t)pn[n] * 32 + lane];
        acc.x += a * gv.x; acc.y += a * gv.y;
        acc.z += a * gv.z; acc.w += a * gv.w;
    }
    ((float4*)g_wa)[(size_t)p * 32 + lane] = acc;
}

// ---------------------------------------------------------------------------
// Pass 3 (tensor): out = x + W_back (256x128) @ wa + b_back, layout [B,C,H,W].
// Block: 256 threads, tile 128 ch x 128 px, K=128, k-tile 16.
// grid = (P_TOT/128, 2)
// ---------------------------------------------------------------------------
__global__ __launch_bounds__(256, 2) void pass3_gemm(
    const float* __restrict__ x,
    const float* __restrict__ w_back, const float* __restrict__ b_back,
    float* __restrict__ out)
{
    __shared__ __align__(16) float smbuf[8448];
    float* As = smbuf;                 // [16][136]
    float* Bs = smbuf + 16 * 136;      // [16][136]
    float (*stage)[132] = (float(*)[132])smbuf;   // [64 ch][128 px + pad]

    const int tid  = threadIdx.x;
    const int lane = tid & 31;
    const int warp = tid >> 5;
    const int warp_m = warp >> 2;
    const int warp_n = warp & 3;
    const int q  = lane >> 2;
    const int kl = lane & 3;

    const int p0  = blockIdx.x * 128;
    const int b   = p0 / HWSZ;
    const int hw0 = p0 % HWSZ;
    const int c0  = blockIdx.y * 128;

    float acc[4][4][4];
#pragma unroll
    for (int mt = 0; mt < 4; ++mt)
#pragma unroll
        for (int nt = 0; nt < 4; ++nt)
#pragma unroll
            for (int i = 0; i < 4; ++i) acc[mt][nt][i] = 0.f;

    const float4* w4  = (const float4*)w_back;   // [256][C_O/4]
    const float4* wa4 = (const float4*)g_wa;     // [P][C_O/4]

    for (int k0 = 0; k0 < C_O; k0 += 16) {
        __syncthreads();
        // A tile: w_back rows c0..c0+127 -> As[k][c]
        {
            int m = tid >> 1;
            int half = tid & 1;
#pragma unroll
            for (int i = 0; i < 2; ++i) {
                int kq = half * 2 + i;
                float4 v = w4[(size_t)(c0 + m) * (C_O / 4) + (k0 >> 2) + kq];
                int kk = kq * 4;
                As[(kk + 0) * 136 + m] = __uint_as_float(f2tf32(v.x));
                As[(kk + 1) * 136 + m] = __uint_as_float(f2tf32(v.y));
                As[(kk + 2) * 136 + m] = __uint_as_float(f2tf32(v.z));
                As[(kk + 3) * 136 + m] = __uint_as_float(f2tf32(v.w));
            }
        }
        // B tile: wa pixel-major -> transpose into Bs[k][px]
        {
            int px = tid >> 1;
            int half = tid & 1;
#pragma unroll
            for (int i = 0; i < 2; ++i) {
                int kq = half * 2 + i;
                float4 v = wa4[(size_t)(p0 + px) * (C_O / 4) + (k0 >> 2) + kq];
                int kk = kq * 4;
                Bs[(kk + 0) * 136 + px] = __uint_as_float(f2tf32(v.x));
                Bs[(kk + 1) * 136 + px] = __uint_as_float(f2tf32(v.y));
                Bs[(kk + 2) * 136 + px] = __uint_as_float(f2tf32(v.z));
                Bs[(kk + 3) * 136 + px] = __uint_as_float(f2tf32(v.w));
            }
        }
        __syncthreads();
#pragma unroll
        for (int ks = 0; ks < 16; ks += 8) {
            int kq = ks + kl;
            uint32_t af[4][4];
            uint32_t bf[4][2];
#pragma unroll
            for (int mt = 0; mt < 4; ++mt) {
                int m = warp_m * 64 + mt * 16 + q;
                af[mt][0] = __float_as_uint(As[kq * 136 + m]);
                af[mt][1] = __float_as_uint(As[kq * 136 + m + 8]);
                af[mt][2] = __float_as_uint(As[(kq + 4) * 136 + m]);
                af[mt][3] = __float_as_uint(As[(kq + 4) * 136 + m + 8]);
            }
#pragma unroll
            for (int nt = 0; nt < 4; ++nt) {
                int pc = warp_n * 32 + nt * 8 + q;
                bf[nt][0] = __float_as_uint(Bs[kq * 136 + pc]);
                bf[nt][1] = __float_as_uint(Bs[(kq + 4) * 136 + pc]);
            }
#pragma unroll
            for (int mt = 0; mt < 4; ++mt)
#pragma unroll
                for (int nt = 0; nt < 4; ++nt)
                    mma_tf32(acc[mt][nt], af[mt][0], af[mt][1], af[mt][2], af[mt][3],
                             bf[nt][0], bf[nt][1]);
        }
    }

    // Epilogue: stage [ch][px], then coalesced residual-add + store
#pragma unroll
    for (int h = 0; h < 2; ++h) {
        __syncthreads();
        if (warp_m == h) {
#pragma unroll
            for (int mt = 0; mt < 4; ++mt)
#pragma unroll
                for (int nt = 0; nt < 4; ++nt)
#pragma unroll
                    for (int hi = 0; hi < 2; ++hi) {
                        int ch = mt * 16 + q + 8 * hi;
                        int px = warp_n * 32 + nt * 8 + 2 * kl;
                        float2 v2 = make_float2(acc[mt][nt][hi * 2], acc[mt][nt][hi * 2 + 1]);
                        *(float2*)&stage[ch][px] = v2;
                    }
        }
        __syncthreads();
#pragma unroll
        for (int it = 0; it < 8; ++it) {
            int g = tid + it * 256;
            int ch = g >> 5;          // 0..63
            int f  = g & 31;          // f4 along 128 px
            int c  = c0 + h * 64 + ch;
            size_t gi = (((size_t)(b * C_IN + c)) * HWSZ + hw0) / 4 + f;
            float4 s = *(float4*)&stage[ch][f * 4];
            float4 xv = ((const float4*)x)[gi];
            float bb = b_back[c];
            float4 o4;
            o4.x = xv.x + bb + s.x;
            o4.y = xv.y + bb + s.y;
            o4.z = xv.z + bb + s.z;
            o4.w = xv.w + bb + s.w;
            ((float4*)out)[gi] = o4;
        }
    }
}

// ---------------------------------------------------------------------------
extern "C" void kernel_launch(void* const* d_in, const int* in_sizes, int n_in,
                              void* d_out, int out_size)
{
    const float* x       = (const float*)d_in[0];
    const float* w_theta = (const float*)d_in[1];
    const float* b_theta = (const float*)d_in[2];
    const float* w_phi   = (const float*)d_in[3];
    const float* b_phi   = (const float*)d_in[4];
    const float* w_g     = (const float*)d_in[5];
    const float* b_g     = (const float*)d_in[6];
    const float* w_back  = (const float*)d_in[7];
    const float* b_back  = (const float*)d_in[8];
    float* out = (float*)d_out;

    dim3 g1(P_TOT / 128, 3, 1);
    pass1_gemm<<<g1, 256>>>(x, w_theta, b_theta, w_phi, b_phi, w_g, b_g);

    pass2_attn<<<P_TOT / 8, 256>>>();

    dim3 g3(P_TOT / 128, 2, 1);
    pass3_gemm<<<g3, 256>>>(x, w_back, b_back, out);
}